// round 13
// baseline (speedup 1.0000x reference)
#include <cuda_runtime.h>
#include <math.h>

#define CH 28
#define CP 32                      // padded channel stride (128B voxel rows)
#define INV_SQ8 0.35355339059327373f
#define NMAX 1050000
#define SCHUNK 2048                // points per scatter block
#define NBLK 148                   // persistent blocks (1 per SM, all resident)
#define PLANE (128 * 128 * CP)     // floats per z-plane (2 MB)
#define SLOT  (16 * PLANE)         // floats per 16-plane ring slot (33.5 MB)
#define NPHASE 10                  // 8 produce phases, queries trail by 2

// Scratch (allocation-free contract: __device__ globals)
__device__ float  g_vol1[CH * 32 * 32 * 32];   //  3.5 MB
__device__ float  g_vol2[CH * 64 * 64 * 64];   //   28 MB
__device__ float  g_ring[3 * SLOT];            // 100.7 MB ring (fits L2)
__device__ float4 g_sorted[NMAX];
__device__ int    g_hist[128];
__device__ int    g_cursor[128];
__device__ int    g_bar;
__device__ int    g_pctr[8];
__device__ int    g_qctr[8];

// ---------------------------------------------------------------------------
// Sort chain: bucket points by z0 (127 bins), block-aggregated counting sort.
// ---------------------------------------------------------------------------
__device__ __forceinline__ int zbin(float z) {
    float pz = (z / 1.5f + 1.0f) * 63.5f;
    return min(max((int)floorf(pz), 0), 126);
}

__global__ void zero_all_kernel() {
    int t = threadIdx.x;
    if (t < 128) g_hist[t] = 0;
    if (t < 8) { g_pctr[t] = 0; g_qctr[t] = 0; }
    if (t == 0) g_bar = 0;
}

__global__ void hist_kernel(const float* __restrict__ xyz, int N) {
    __shared__ int sh[128];
    if (threadIdx.x < 128) sh[threadIdx.x] = 0;
    __syncthreads();
    for (int i = blockIdx.x * blockDim.x + threadIdx.x; i < N;
         i += gridDim.x * blockDim.x)
        atomicAdd(&sh[zbin(xyz[3 * i + 2])], 1);
    __syncthreads();
    if (threadIdx.x < 128 && sh[threadIdx.x])
        atomicAdd(&g_hist[threadIdx.x], sh[threadIdx.x]);
}

__global__ void scan_kernel() {
    __shared__ int s[128];
    int t = threadIdx.x;            // blockDim = 128
    int v = g_hist[t];
    s[t] = v;
    __syncthreads();
#pragma unroll
    for (int off = 1; off < 128; off <<= 1) {
        int u = (t >= off) ? s[t - off] : 0;
        __syncthreads();
        s[t] += u;
        __syncthreads();
    }
    g_cursor[t] = s[t] - v;         // exclusive prefix; scatter -> inclusive end
}

__global__ void scatter_kernel(const float* __restrict__ xyz, int N) {
    __shared__ int sh_count[128];
    __shared__ int sh_base[128];

    int tid = threadIdx.x;
    if (tid < 128) sh_count[tid] = 0;
    __syncthreads();

    int start = blockIdx.x * SCHUNK;
    float px[8], py[8], pz[8];
    int code[8];

#pragma unroll
    for (int it = 0; it < 8; it++) {
        int i = start + it * 256 + tid;
        code[it] = -1;
        if (i < N) {
            px[it] = xyz[3 * i + 0];
            py[it] = xyz[3 * i + 1];
            pz[it] = xyz[3 * i + 2];
            int b = zbin(pz[it]);
            int r = atomicAdd(&sh_count[b], 1);
            code[it] = (b << 16) | r;
        }
    }
    __syncthreads();

    if (tid < 128) {
        int c = sh_count[tid];
        sh_base[tid] = c ? atomicAdd(&g_cursor[tid], c) : 0;
    }
    __syncthreads();

#pragma unroll
    for (int it = 0; it < 8; it++) {
        if (code[it] >= 0) {
            int b = code[it] >> 16, r = code[it] & 0xFFFF;
            int i = start + it * 256 + tid;
            g_sorted[sh_base[b] + r] =
                make_float4(px[it], py[it], pz[it], __int_as_float(i));
        }
    }
}

// ---------------------------------------------------------------------------
// Small IDWT levels, channel-major fp32 output.
// ---------------------------------------------------------------------------
template <int D>
__global__ void idwt_small(const float* __restrict__ approx,
                           const float* __restrict__ det,
                           float* __restrict__ out) {
    const int vol = CH * D * D * D;
    int idx = blockIdx.x * blockDim.x + threadIdx.x;
    if (idx >= vol) return;
    int k = idx % D;
    int j = (idx / D) % D;
    int i = (idx / (D * D)) % D;
    int c = idx / (D * D * D);

    float a[8];
    a[0] = approx[idx];
#pragma unroll
    for (int s = 1; s < 8; s++) a[s] = det[(size_t)(s - 1) * vol + idx];

    const int R = 2 * D;
    size_t base = (((size_t)c * R + 2 * i) * R + 2 * j) * R + 2 * k;
#pragma unroll
    for (int p = 0; p < 2; p++)
#pragma unroll
        for (int q = 0; q < 2; q++) {
            float b0 = 0.f, b1 = 0.f;
#pragma unroll
            for (int u = 0; u < 2; u++)
#pragma unroll
                for (int v = 0; v < 2; v++) {
                    float sgn = ((u & p) ^ (v & q)) ? -1.f : 1.f;
                    b0 += sgn * a[u * 4 + v * 2 + 0];
                    b1 += sgn * a[u * 4 + v * 2 + 1];
                }
            float2 val = make_float2(INV_SQ8 * (b0 + b1), INV_SQ8 * (b0 - b1));
            *(float2*)(out + base + ((size_t)p * R + q) * R) = val;
        }
}

// ---------------------------------------------------------------------------
// Persistent fused final-IDWT + query. Phase p (<8) produces 16-plane chunk p
// into ring slot p%3; phase p (>=2) queries chunk p-2 (planes complete incl.
// boundary). Global software barrier between phases (all 148 blocks resident).
// ---------------------------------------------------------------------------
__device__ __forceinline__ float4* plane4(int z) {
    return (float4*)g_ring +
           (size_t)((z >> 4) % 3) * (SLOT / 4) + (size_t)(z & 15) * (PLANE / 4);
}

__global__ __launch_bounds__(256, 1)
void fused_kernel(const float* __restrict__ approx,      // g_vol2 (64^3)
                  const float* __restrict__ det,         // det2
                  float* __restrict__ out) {
    const int D = 64;
    const int vol = CH * D * D * D;
    int tid = threadIdx.x;
    __shared__ __align__(16) float sh[4][16 * CH + 32];
    __shared__ int s_work;

    for (int phase = 0; phase < NPHASE; phase++) {
        // ---- produce chunk = phase (coarse i in [8*phase, 8*phase+8)) ----
        if (phase < 8) {
            for (;;) {
                __syncthreads();
                if (tid == 0) s_work = atomicAdd(&g_pctr[phase], 1);
                __syncthreads();
                int t = s_work;
                if (t >= 4096) break;
                int ktile = t & 7;
                int j = (t >> 3) & 63;
                int i = phase * 8 + (t >> 9);
                int k0 = ktile * 8;

                int c  = tid >> 3;
                int kl = tid & 7;
                if (c < CH) {
                    int idx = ((c * D + i) * D + j) * D + k0 + kl;
                    float a[8];
                    a[0] = __ldcs(approx + idx);
#pragma unroll
                    for (int s = 1; s < 8; s++)
                        a[s] = __ldcs(det + (size_t)(s - 1) * vol + idx);
#pragma unroll
                    for (int p = 0; p < 2; p++)
#pragma unroll
                        for (int q = 0; q < 2; q++) {
                            float b0 = 0.f, b1 = 0.f;
#pragma unroll
                            for (int u = 0; u < 2; u++)
#pragma unroll
                                for (int v = 0; v < 2; v++) {
                                    float sgn = ((u & p) ^ (v & q)) ? -1.f : 1.f;
                                    b0 += sgn * a[u * 4 + v * 2 + 0];
                                    b1 += sgn * a[u * 4 + v * 2 + 1];
                                }
                            sh[p * 2 + q][(2 * kl + 0) * CH + c] = INV_SQ8 * (b0 + b1);
                            sh[p * 2 + q][(2 * kl + 1) * CH + c] = INV_SQ8 * (b0 - b1);
                        }
                }
                __syncthreads();

                // 512 float4 stores: 4 octants x 16 x-values x 8 quads.
#pragma unroll
                for (int t2 = tid; t2 < 512; t2 += 256) {
                    int pq = t2 >> 7;
                    int r  = t2 & 127;          // x*8 + f4
                    int x  = r >> 3, f4 = r & 7;
                    int p = pq >> 1, q = pq & 1;
                    int z = 2 * i + p, y = 2 * j + q;
                    float4 val = make_float4(0.f, 0.f, 0.f, 0.f);
                    if (f4 < 7) {
                        const float* src = &sh[pq][x * CH + 4 * f4];
                        val = make_float4(src[0], src[1], src[2], src[3]);
                    }
                    float4* bp = plane4(z) + ((size_t)y * 128 + 2 * k0) * (CP / 4);
                    bp[r] = val;
                }
            }
        }

        // ---- query chunk = phase - 2 (bins [16c, 16c+16)) ----
        if (phase >= 2) {
            int cN = phase - 2;
            int qs = (cN == 0) ? 0 : g_cursor[16 * cN - 1];
            int qe = g_cursor[16 * cN + 15];
            int w = tid >> 5, lane = tid & 31, l = lane & 7;
            for (;;) {
                __syncthreads();
                if (tid == 0) s_work = atomicAdd(&g_qctr[cN], 1);
                __syncthreads();
                int base = qs + s_work * 256;
                if (base >= qe) break;
#pragma unroll
                for (int it = 0; it < 8; it++) {
                    int pt = base + w * 32 + it * 4 + (lane >> 3);
                    if (pt >= qe || l >= CH / 4) continue;

                    float4 s = g_sorted[pt];
                    int idx = __float_as_int(s.w);

                    float px = (s.x / 1.5f + 1.0f) * 63.5f;
                    float py = (s.y / 1.5f + 1.0f) * 63.5f;
                    float pz = (s.z / 1.5f + 1.0f) * 63.5f;
                    float flx = floorf(px), fly = floorf(py), flz = floorf(pz);
                    float fx = px - flx, fy = py - fly, fz = pz - flz;
                    int x0 = min(max((int)flx, 0), 126);
                    int y0 = min(max((int)fly, 0), 126);
                    int z0 = min(max((int)flz, 0), 126);

                    float wx1 = fx, wx0 = 1.f - fx;
                    float wy1 = fy, wy0 = 1.f - fy;
                    float wz1 = fz, wz0 = 1.f - fz;
                    float w00 = wz0 * wy0, w01 = wz0 * wy1;
                    float w10 = wz1 * wy0, w11 = wz1 * wy1;

                    size_t oyx = ((size_t)y0 * 128 + x0) * (CP / 4) + l;
                    const float4* b0 = plane4(z0) + oyx;
                    const float4* b1 = plane4(z0 + 1) + oyx;
                    const size_t DX = CP / 4, DY = (size_t)128 * (CP / 4);

                    // __ldcg: bypass L1 (ring slots are rewritten by other SMs)
                    float4 v000 = __ldcg(b0);
                    float4 v001 = __ldcg(b0 + DX);
                    float4 v010 = __ldcg(b0 + DY);
                    float4 v011 = __ldcg(b0 + DY + DX);
                    float4 v100 = __ldcg(b1);
                    float4 v101 = __ldcg(b1 + DX);
                    float4 v110 = __ldcg(b1 + DY);
                    float4 v111 = __ldcg(b1 + DY + DX);

                    float4 r;
                    r.x = w00 * (wx0 * v000.x + wx1 * v001.x) + w01 * (wx0 * v010.x + wx1 * v011.x) +
                          w10 * (wx0 * v100.x + wx1 * v101.x) + w11 * (wx0 * v110.x + wx1 * v111.x);
                    r.y = w00 * (wx0 * v000.y + wx1 * v001.y) + w01 * (wx0 * v010.y + wx1 * v011.y) +
                          w10 * (wx0 * v100.y + wx1 * v101.y) + w11 * (wx0 * v110.y + wx1 * v111.y);
                    r.z = w00 * (wx0 * v000.z + wx1 * v001.z) + w01 * (wx0 * v010.z + wx1 * v011.z) +
                          w10 * (wx0 * v100.z + wx1 * v101.z) + w11 * (wx0 * v110.z + wx1 * v111.z);
                    r.w = w00 * (wx0 * v000.w + wx1 * v001.w) + w01 * (wx0 * v010.w + wx1 * v011.w) +
                          w10 * (wx0 * v100.w + wx1 * v101.w) + w11 * (wx0 * v110.w + wx1 * v111.w);

                    __stcs((float4*)(out + (size_t)idx * CH) + l, r);
                }
            }
        }

        // ---- global barrier (all NBLK blocks resident by construction) ----
        if (phase < NPHASE - 1) {
            __threadfence();
            __syncthreads();
            if (tid == 0) {
                atomicAdd(&g_bar, 1);
                int target = NBLK * (phase + 1);
                while (atomicAdd(&g_bar, 0) < target) __nanosleep(64);
            }
            __syncthreads();
        }
    }
}

extern "C" void kernel_launch(void* const* d_in, const int* in_sizes, int n_in,
                              void* d_out, int out_size) {
    const float* approx = (const float*)d_in[0];   // (28,16,16,16)
    const float* det0   = (const float*)d_in[1];   // (7,28,16,16,16)
    const float* det1   = (const float*)d_in[2];   // (7,28,32,32,32)
    const float* det2   = (const float*)d_in[3];   // (7,28,64,64,64)
    const float* xyz    = (const float*)d_in[4];   // (N,3)
    int N = in_sizes[4] / 3;

    float *vol1, *vol2;
    cudaGetSymbolAddress((void**)&vol1, g_vol1);
    cudaGetSymbolAddress((void**)&vol2, g_vol2);

    // Sort chain (also zeroes barrier/counters for this replay)
    zero_all_kernel<<<1, 256>>>();
    hist_kernel<<<448, 256>>>(xyz, N);
    scan_kernel<<<1, 128>>>();
    scatter_kernel<<<(N + SCHUNK - 1) / SCHUNK, 256>>>(xyz, N);

    {   // level 0: 16 -> 32
        int n = CH * 16 * 16 * 16;
        idwt_small<16><<<(n + 255) / 256, 256>>>(approx, det0, vol1);
    }
    {   // level 1: 32 -> 64
        int n = CH * 32 * 32 * 32;
        idwt_small<32><<<(n + 255) / 256, 256>>>(vol1, det1, vol2);
    }

    // Persistent fused final IDWT + trilinear query (ring stays in L2)
    fused_kernel<<<NBLK, 256>>>(vol2, det2, (float*)d_out);
}

// round 15
// speedup vs baseline: 1.4371x; 1.4371x over previous
#include <cuda_runtime.h>
#include <math.h>

#define CH 28
#define CP 32          // padded channel stride: 128B voxel rows
#define INV_SQ8 0.35355339059327373f
#define NMAX 1050000
#define SCHUNK 2048    // points per scatter block
#define NPROD 32768    // producer blocks: 64 i x 64 j x 8 ktile
#define NCONS 32768    // consumer blocks: 32 points each (covers 1.05M)
#define PHEAD 1024     // producer head-start blocks (i = 0..1)

// Scratch (allocation-free contract: __device__ globals)
__device__ float  g_vol1[CH * 32 * 32 * 32];             //  3.5 MB
__device__ float  g_vol2[CH * 64 * 64 * 64];             //   28 MB
__device__ float  g_volF[(size_t)128 * 128 * 128 * CP];  //  268 MB (z,y,x,32)
__device__ float4 g_sorted[NMAX];                        // z-sorted (x,y,z,idx)
__device__ int    g_hist[128];
__device__ int    g_cursor[128];
__device__ int    g_done_i[64];    // per coarse-i (plane pair) completion, target 512

// ---------------------------------------------------------------------------
// Sort chain: bucket points by z0 (127 bins), block-aggregated counting sort.
// ---------------------------------------------------------------------------
__device__ __forceinline__ int zbin(float z) {
    float pz = (z / 1.5f + 1.0f) * 63.5f;
    return min(max((int)floorf(pz), 0), 126);
}

__global__ void zero_all_kernel() {
    int t = threadIdx.x;
    if (t < 128) g_hist[t] = 0;
    if (t < 64) g_done_i[t] = 0;
}

__global__ void hist_kernel(const float* __restrict__ xyz, int N) {
    __shared__ int sh[128];
    if (threadIdx.x < 128) sh[threadIdx.x] = 0;
    __syncthreads();
    for (int i = blockIdx.x * blockDim.x + threadIdx.x; i < N;
         i += gridDim.x * blockDim.x)
        atomicAdd(&sh[zbin(xyz[3 * i + 2])], 1);
    __syncthreads();
    if (threadIdx.x < 128 && sh[threadIdx.x])
        atomicAdd(&g_hist[threadIdx.x], sh[threadIdx.x]);
}

__global__ void scan_kernel() {
    __shared__ int s[128];
    int t = threadIdx.x;            // blockDim = 128
    int v = g_hist[t];
    s[t] = v;
    __syncthreads();
#pragma unroll
    for (int off = 1; off < 128; off <<= 1) {
        int u = (t >= off) ? s[t - off] : 0;
        __syncthreads();
        s[t] += u;
        __syncthreads();
    }
    g_cursor[t] = s[t] - v;         // exclusive prefix
}

__global__ void scatter_kernel(const float* __restrict__ xyz, int N) {
    __shared__ int sh_count[128];
    __shared__ int sh_base[128];

    int tid = threadIdx.x;
    if (tid < 128) sh_count[tid] = 0;
    __syncthreads();

    int start = blockIdx.x * SCHUNK;
    float px[8], py[8], pz[8];
    int code[8];

#pragma unroll
    for (int it = 0; it < 8; it++) {
        int i = start + it * 256 + tid;
        code[it] = -1;
        if (i < N) {
            px[it] = xyz[3 * i + 0];
            py[it] = xyz[3 * i + 1];
            pz[it] = xyz[3 * i + 2];
            int b = zbin(pz[it]);
            int r = atomicAdd(&sh_count[b], 1);
            code[it] = (b << 16) | r;
        }
    }
    __syncthreads();

    if (tid < 128) {
        int c = sh_count[tid];
        sh_base[tid] = c ? atomicAdd(&g_cursor[tid], c) : 0;
    }
    __syncthreads();

#pragma unroll
    for (int it = 0; it < 8; it++) {
        if (code[it] >= 0) {
            int b = code[it] >> 16, r = code[it] & 0xFFFF;
            int i = start + it * 256 + tid;
            g_sorted[sh_base[b] + r] =
                make_float4(px[it], py[it], pz[it], __int_as_float(i));
        }
    }
}

// ---------------------------------------------------------------------------
// Small IDWT levels, channel-major fp32 output.
// ---------------------------------------------------------------------------
template <int D>
__global__ void idwt_small(const float* __restrict__ approx,
                           const float* __restrict__ det,
                           float* __restrict__ out) {
    const int vol = CH * D * D * D;
    int idx = blockIdx.x * blockDim.x + threadIdx.x;
    if (idx >= vol) return;
    int k = idx % D;
    int j = (idx / D) % D;
    int i = (idx / (D * D)) % D;
    int c = idx / (D * D * D);

    float a[8];
    a[0] = approx[idx];
#pragma unroll
    for (int s = 1; s < 8; s++) a[s] = det[(size_t)(s - 1) * vol + idx];

    const int R = 2 * D;
    size_t base = (((size_t)c * R + 2 * i) * R + 2 * j) * R + 2 * k;
#pragma unroll
    for (int p = 0; p < 2; p++)
#pragma unroll
        for (int q = 0; q < 2; q++) {
            float b0 = 0.f, b1 = 0.f;
#pragma unroll
            for (int u = 0; u < 2; u++)
#pragma unroll
                for (int v = 0; v < 2; v++) {
                    float sgn = ((u & p) ^ (v & q)) ? -1.f : 1.f;
                    b0 += sgn * a[u * 4 + v * 2 + 0];
                    b1 += sgn * a[u * 4 + v * 2 + 1];
                }
            float2 val = make_float2(INV_SQ8 * (b0 + b1), INV_SQ8 * (b0 - b1));
            *(float2*)(out + base + ((size_t)p * R + q) * R) = val;
        }
}

// ---------------------------------------------------------------------------
// Fused pipelined final-IDWT + query in ONE grid. Block roles by bid:
//   [0, PHEAD)            : producer tiles t = bid            (i = 0..1)
//   [PHEAD, 64512) even r : producer tiles t = PHEAD + r/2    (i ascending)
//   [PHEAD, 64512) odd  r : consumer block c = r/2            (bins ascending)
//   [64512, 65536)        : consumer blocks c = 31744 + ...
// In-order CTA dispatch => every producer a consumer needs is dispatched
// earlier => no deadlock; spin is bounded. Flags: g_done_i[i] (512 tiles).
// ---------------------------------------------------------------------------
__global__ __launch_bounds__(256)
void fused_kernel(const float* __restrict__ approx,   // g_vol2 (64^3 ch-major)
                  const float* __restrict__ det,      // det2
                  const float* __restrict__ volc,     // g_volF (const alias)
                  float* __restrict__ volp,           // g_volF (producer writes)
                  float* __restrict__ out, int N) {
    const int D = 64, R = 128;
    const int vol = CH * D * D * D;
    int bid = blockIdx.x;
    int tid = threadIdx.x;

    int ptile = -1, cons = -1;
    if (bid < PHEAD) {
        ptile = bid;
    } else {
        int r = bid - PHEAD;
        int h = r >> 1;
        if ((r & 1) == 0 && (PHEAD + h) < NPROD) ptile = PHEAD + h;
        else if ((r & 1) == 1)                    cons = h;
        else                                      cons = (NPROD - PHEAD) + (r - 2 * (NPROD - PHEAD));
    }

    if (ptile >= 0) {
        // ---------------- producer: one IDWT tile ----------------
        int t = ptile;
        int ktile = t & 7;
        int j = (t >> 3) & 63;
        int i = t >> 9;              // 0..63, ascending with bid
        int k0 = ktile * 8;

        __shared__ __align__(16) float sh[4][16 * CH + 32];
        int c  = tid >> 3;
        int kl = tid & 7;
        if (c < CH) {
            int idx = ((c * D + i) * D + j) * D + k0 + kl;
            float a[8];
            a[0] = __ldcs(approx + idx);
#pragma unroll
            for (int s = 1; s < 8; s++)
                a[s] = __ldcs(det + (size_t)(s - 1) * vol + idx);
#pragma unroll
            for (int p = 0; p < 2; p++)
#pragma unroll
                for (int q = 0; q < 2; q++) {
                    float b0 = 0.f, b1 = 0.f;
#pragma unroll
                    for (int u = 0; u < 2; u++)
#pragma unroll
                        for (int v = 0; v < 2; v++) {
                            float sgn = ((u & p) ^ (v & q)) ? -1.f : 1.f;
                            b0 += sgn * a[u * 4 + v * 2 + 0];
                            b1 += sgn * a[u * 4 + v * 2 + 1];
                        }
                    sh[p * 2 + q][(2 * kl + 0) * CH + c] = INV_SQ8 * (b0 + b1);
                    sh[p * 2 + q][(2 * kl + 1) * CH + c] = INV_SQ8 * (b0 - b1);
                }
        }
        __syncthreads();

#pragma unroll
        for (int t2 = tid; t2 < 512; t2 += 256) {
            int pq = t2 >> 7;
            int r2 = t2 & 127;          // x*8 + f4
            int x  = r2 >> 3, f4 = r2 & 7;
            int p = pq >> 1, q = pq & 1;
            size_t base = (((size_t)(2 * i + p) * R + (2 * j + q)) * R + 2 * k0) * CP;
            float4 val = make_float4(0.f, 0.f, 0.f, 0.f);
            if (f4 < 7) {
                const float* src = &sh[pq][x * CH + 4 * f4];
                val = make_float4(src[0], src[1], src[2], src[3]);
            }
            ((float4*)(volp + base))[r2] = val;
        }

        __threadfence();
        __syncthreads();
        if (tid == 0) atomicAdd(&g_done_i[i], 1);
        return;
    }

    // ---------------- consumer: 32 sorted points ----------------
    int start = cons * 32;
    if (start >= N) return;
    int last = min(start + 31, N - 1);

    if (tid == 0) {
        int b0 = zbin(g_sorted[start].z);
        int b1 = zbin(g_sorted[last].z);
        int i_lo = b0 >> 1, i_hi = (b1 + 1) >> 1;   // <= 63
        for (int ii = i_lo; ii <= i_hi; ii++)
            while (atomicAdd(&g_done_i[ii], 0) < 512) __nanosleep(128);
        __threadfence();
    }
    __syncthreads();

    int lane = tid & 31;
    int pt = start + (tid >> 5) * 4 + (lane >> 3);
    int l  = lane & 7;
    if (pt > last || l >= CH / 4) return;

    float4 s = g_sorted[pt];
    int idx = __float_as_int(s.w);

    float px = (s.x / 1.5f + 1.0f) * 63.5f;
    float py = (s.y / 1.5f + 1.0f) * 63.5f;
    float pz = (s.z / 1.5f + 1.0f) * 63.5f;
    float flx = floorf(px), fly = floorf(py), flz = floorf(pz);
    float fx = px - flx, fy = py - fly, fz = pz - flz;
    int x0 = min(max((int)flx, 0), 126);
    int y0 = min(max((int)fly, 0), 126);
    int z0 = min(max((int)flz, 0), 126);

    float wx1 = fx, wx0 = 1.f - fx;
    float wy1 = fy, wy0 = 1.f - fy;
    float wz1 = fz, wz0 = 1.f - fz;
    float w00 = wz0 * wy0, w01 = wz0 * wy1, w10 = wz1 * wy0, w11 = wz1 * wy1;

    const float4* base = (const float4*)volc +
                         (((size_t)z0 * 128 + y0) * 128 + x0) * (CP / 4) + l;
    const size_t DX = CP / 4;
    const size_t DY = (size_t)128 * (CP / 4);
    const size_t DZ = (size_t)128 * 128 * (CP / 4);

    float4 v000 = base[0];
    float4 v001 = base[DX];
    float4 v010 = base[DY];
    float4 v011 = base[DY + DX];
    float4 v100 = base[DZ];
    float4 v101 = base[DZ + DX];
    float4 v110 = base[DZ + DY];
    float4 v111 = base[DZ + DY + DX];

    float4 r;
    r.x = w00 * (wx0 * v000.x + wx1 * v001.x) + w01 * (wx0 * v010.x + wx1 * v011.x) +
          w10 * (wx0 * v100.x + wx1 * v101.x) + w11 * (wx0 * v110.x + wx1 * v111.x);
    r.y = w00 * (wx0 * v000.y + wx1 * v001.y) + w01 * (wx0 * v010.y + wx1 * v011.y) +
          w10 * (wx0 * v100.y + wx1 * v101.y) + w11 * (wx0 * v110.y + wx1 * v111.y);
    r.z = w00 * (wx0 * v000.z + wx1 * v001.z) + w01 * (wx0 * v010.z + wx1 * v011.z) +
          w10 * (wx0 * v100.z + wx1 * v101.z) + w11 * (wx0 * v110.z + wx1 * v111.z);
    r.w = w00 * (wx0 * v000.w + wx1 * v001.w) + w01 * (wx0 * v010.w + wx1 * v011.w) +
          w10 * (wx0 * v100.w + wx1 * v101.w) + w11 * (wx0 * v110.w + wx1 * v111.w);

    __stcs((float4*)(out + (size_t)idx * CH) + l, r);
}

extern "C" void kernel_launch(void* const* d_in, const int* in_sizes, int n_in,
                              void* d_out, int out_size) {
    const float* approx = (const float*)d_in[0];   // (28,16,16,16)
    const float* det0   = (const float*)d_in[1];   // (7,28,16,16,16)
    const float* det1   = (const float*)d_in[2];   // (7,28,32,32,32)
    const float* det2   = (const float*)d_in[3];   // (7,28,64,64,64)
    const float* xyz    = (const float*)d_in[4];   // (N,3)
    int N = in_sizes[4] / 3;

    float *vol1, *vol2, *volF;
    cudaGetSymbolAddress((void**)&vol1, g_vol1);
    cudaGetSymbolAddress((void**)&vol2, g_vol2);
    cudaGetSymbolAddress((void**)&volF, g_volF);

    // Sort chain (zero_all also resets pipeline flags each replay)
    zero_all_kernel<<<1, 128>>>();
    hist_kernel<<<448, 256>>>(xyz, N);
    scan_kernel<<<1, 128>>>();
    scatter_kernel<<<(N + SCHUNK - 1) / SCHUNK, 256>>>(xyz, N);

    {   // level 0: 16 -> 32
        int n = CH * 16 * 16 * 16;
        idwt_small<16><<<(n + 255) / 256, 256>>>(approx, det0, vol1);
    }
    {   // level 1: 32 -> 64
        int n = CH * 32 * 32 * 32;
        idwt_small<32><<<(n + 255) / 256, 256>>>(vol1, det1, vol2);
    }

    // Pipelined final IDWT + query: one grid, producers/consumers interleaved
    fused_kernel<<<PHEAD + 2 * (NPROD - PHEAD) + (NCONS - (NPROD - PHEAD)), 256>>>(
        vol2, det2, volF, volF, (float*)d_out, N);
}

// round 16
// speedup vs baseline: 2.4120x; 1.6784x over previous
#include <cuda_runtime.h>
#include <math.h>

#define CH 28
#define CP 32          // padded channel stride: 128B voxel rows
#define INV_SQ8 0.35355339059327373f
#define NMAX 1050000
#define SCHUNK 2048    // points per scatter block (256 thr x 8)
#define NBIN 4096      // 16 x 16 x 16 tiles of 8^3 voxels (z-major order)

// Scratch (allocation-free contract: __device__ globals)
__device__ float  g_vol1[CH * 32 * 32 * 32];             //  3.5 MB
__device__ float  g_vol2[CH * 64 * 64 * 64];             //   28 MB
__device__ float  g_volF[(size_t)128 * 128 * 128 * CP];  //  268 MB (z,y,x,32)
__device__ float4 g_sorted[NMAX];                        // tile-sorted (x,y,z,idx)
__device__ int    g_hist[NBIN];
__device__ int    g_cursor[NBIN];

// ---------------------------------------------------------------------------
// 3D tile binning: bin = zt*256 + yt*16 + xt (z-major), tile = 8^3 voxels.
// A tile's gather footprint is 9^3 lines = 93 KB -> fits one SM's L1.
// ---------------------------------------------------------------------------
__device__ __forceinline__ int bin3(float x, float y, float z) {
    float px = (x / 1.5f + 1.0f) * 63.5f;
    float py = (y / 1.5f + 1.0f) * 63.5f;
    float pz = (z / 1.5f + 1.0f) * 63.5f;
    int x0 = min(max((int)floorf(px), 0), 126);
    int y0 = min(max((int)floorf(py), 0), 126);
    int z0 = min(max((int)floorf(pz), 0), 126);
    return ((z0 >> 3) << 8) | ((y0 >> 3) << 4) | (x0 >> 3);
}

__global__ void zero_hist_kernel() {      // 1024 threads
    int t = threadIdx.x;
#pragma unroll
    for (int i = 0; i < 4; i++) g_hist[t + i * 1024] = 0;
}

__global__ void hist_kernel(const float* __restrict__ xyz, int N) {
    __shared__ int sh[NBIN];
    for (int b = threadIdx.x; b < NBIN; b += blockDim.x) sh[b] = 0;
    __syncthreads();
    for (int i = blockIdx.x * blockDim.x + threadIdx.x; i < N;
         i += gridDim.x * blockDim.x)
        atomicAdd(&sh[bin3(xyz[3 * i], xyz[3 * i + 1], xyz[3 * i + 2])], 1);
    __syncthreads();
    for (int b = threadIdx.x; b < NBIN; b += blockDim.x)
        if (sh[b]) atomicAdd(&g_hist[b], sh[b]);
}

__global__ void scan_kernel() {           // 1024 threads, scans 4096
    __shared__ int ws[1024];
    int t = threadIdx.x;
    int4 v = ((const int4*)g_hist)[t];    // 4 consecutive bins
    int sum = v.x + v.y + v.z + v.w;
    ws[t] = sum;
    __syncthreads();
#pragma unroll
    for (int off = 1; off < 1024; off <<= 1) {
        int u = (t >= off) ? ws[t - off] : 0;
        __syncthreads();
        ws[t] += u;
        __syncthreads();
    }
    int base = ws[t] - sum;               // exclusive prefix of this group
    g_cursor[4 * t + 0] = base;
    g_cursor[4 * t + 1] = base + v.x;
    g_cursor[4 * t + 2] = base + v.x + v.y;
    g_cursor[4 * t + 3] = base + v.x + v.y + v.z;
}

// Block-aggregated scatter: local ranks via smem atomics, one global
// atomicAdd per (block, nonempty bin). After this, g_cursor = inclusive ends.
__global__ void scatter_kernel(const float* __restrict__ xyz, int N) {
    __shared__ int sh_count[NBIN];
    __shared__ int sh_base[NBIN];

    int tid = threadIdx.x;
    for (int b = tid; b < NBIN; b += 256) sh_count[b] = 0;
    __syncthreads();

    int start = blockIdx.x * SCHUNK;
    float px[8], py[8], pz[8];
    int code[8];                          // bin<<12 | local_rank

#pragma unroll
    for (int it = 0; it < 8; it++) {
        int i = start + it * 256 + tid;
        code[it] = -1;
        if (i < N) {
            px[it] = xyz[3 * i + 0];
            py[it] = xyz[3 * i + 1];
            pz[it] = xyz[3 * i + 2];
            int b = bin3(px[it], py[it], pz[it]);
            int r = atomicAdd(&sh_count[b], 1);
            code[it] = (b << 12) | r;
        }
    }
    __syncthreads();

    for (int b = tid; b < NBIN; b += 256) {
        int c = sh_count[b];
        sh_base[b] = c ? atomicAdd(&g_cursor[b], c) : 0;
    }
    __syncthreads();

#pragma unroll
    for (int it = 0; it < 8; it++) {
        if (code[it] >= 0) {
            int b = code[it] >> 12, r = code[it] & 0xFFF;
            int i = start + it * 256 + tid;
            g_sorted[sh_base[b] + r] =
                make_float4(px[it], py[it], pz[it], __int_as_float(i));
        }
    }
}

// ---------------------------------------------------------------------------
// Small IDWT levels, channel-major fp32 output.
// ---------------------------------------------------------------------------
template <int D>
__global__ void idwt_small(const float* __restrict__ approx,
                           const float* __restrict__ det,
                           float* __restrict__ out) {
    const int vol = CH * D * D * D;
    int idx = blockIdx.x * blockDim.x + threadIdx.x;
    if (idx >= vol) return;
    int k = idx % D;
    int j = (idx / D) % D;
    int i = (idx / (D * D)) % D;
    int c = idx / (D * D * D);

    float a[8];
    a[0] = approx[idx];
#pragma unroll
    for (int s = 1; s < 8; s++) a[s] = det[(size_t)(s - 1) * vol + idx];

    const int R = 2 * D;
    size_t base = (((size_t)c * R + 2 * i) * R + 2 * j) * R + 2 * k;
#pragma unroll
    for (int p = 0; p < 2; p++)
#pragma unroll
        for (int q = 0; q < 2; q++) {
            float b0 = 0.f, b1 = 0.f;
#pragma unroll
            for (int u = 0; u < 2; u++)
#pragma unroll
                for (int v = 0; v < 2; v++) {
                    float sgn = ((u & p) ^ (v & q)) ? -1.f : 1.f;
                    b0 += sgn * a[u * 4 + v * 2 + 0];
                    b1 += sgn * a[u * 4 + v * 2 + 1];
                }
            float2 val = make_float2(INV_SQ8 * (b0 + b1), INV_SQ8 * (b0 - b1));
            *(float2*)(out + base + ((size_t)p * R + q) * R) = val;
        }
}

// ---------------------------------------------------------------------------
// Final IDWT level (64 -> 128) fused with transpose to channel-last padded
// fp32 (z, y, x, 32). z DESCENDING so low-z planes are L2-hot at query start.
// ---------------------------------------------------------------------------
__global__ void idwt_final(const float* __restrict__ approx,
                           const float* __restrict__ det,
                           float* __restrict__ out) {
    const int D = 64, R = 128;
    const int vol = CH * D * D * D;
    int bid = blockIdx.x;
    int ktile = bid & 7;
    int j = (bid >> 3) & 63;
    int i = 63 - (bid >> 9);        // reverse z order
    int k0 = ktile * 8;

    int tid = threadIdx.x;
    int c  = tid >> 3;   // 0..31, only 0..27 active
    int kl = tid & 7;    // 0..7

    __shared__ __align__(16) float sh[4][16 * CH + 32];

    if (c < CH) {
        int idx = ((c * D + i) * D + j) * D + k0 + kl;
        float a[8];
        a[0] = __ldcs(approx + idx);
#pragma unroll
        for (int s = 1; s < 8; s++) a[s] = __ldcs(det + (size_t)(s - 1) * vol + idx);
#pragma unroll
        for (int p = 0; p < 2; p++)
#pragma unroll
            for (int q = 0; q < 2; q++) {
                float b0 = 0.f, b1 = 0.f;
#pragma unroll
                for (int u = 0; u < 2; u++)
#pragma unroll
                    for (int v = 0; v < 2; v++) {
                        float sgn = ((u & p) ^ (v & q)) ? -1.f : 1.f;
                        b0 += sgn * a[u * 4 + v * 2 + 0];
                        b1 += sgn * a[u * 4 + v * 2 + 1];
                    }
                sh[p * 2 + q][(2 * kl + 0) * CH + c] = INV_SQ8 * (b0 + b1);
                sh[p * 2 + q][(2 * kl + 1) * CH + c] = INV_SQ8 * (b0 - b1);
            }
    }
    __syncthreads();

    // 512 float4 stores: 4 octants x 16 x-values x 8 quads (f4==7 = zero pad).
#pragma unroll
    for (int t = tid; t < 512; t += 256) {
        int pq = t >> 7;
        int r  = t & 127;           // x*8 + f4
        int x  = r >> 3, f4 = r & 7;
        int p = pq >> 1, q = pq & 1;
        size_t base = (((size_t)(2 * i + p) * R + (2 * j + q)) * R + 2 * k0) * CP;
        float4 val = make_float4(0.f, 0.f, 0.f, 0.f);
        if (f4 < 7) {
            const float* src = &sh[pq][x * CH + 4 * f4];
            val = make_float4(src[0], src[1], src[2], src[3]);
        }
        ((float4*)(out + base))[r] = val;
    }
}

// ---------------------------------------------------------------------------
// Trilinear query: ONE BLOCK PER 3D TILE. All ~244 points of a tile run on
// one SM; their gathers touch <= 9^3 = 729 lines (93 KB) -> L1-resident,
// capturing the ~3.8x voxel reuse before L2. 4 points per warp, float4/lane.
// ---------------------------------------------------------------------------
__global__ __launch_bounds__(256)
void query_kernel(const float* __restrict__ vol, float* __restrict__ out) {
    int bin = blockIdx.x;
    int start = bin ? g_cursor[bin - 1] : 0;
    int end = g_cursor[bin];

    int tid = threadIdx.x;
    int w = tid >> 5, lane = tid & 31;
    int sub = lane >> 3;            // 0..3: point within warp-group
    int l = lane & 7;               // 0..7, active l<7 (channels 4l..4l+3)

    for (int base_pt = start; base_pt < end; base_pt += 32) {
        int pt = base_pt + w * 4 + sub;
        // note: stride 32 over 8 warps x 4 pts => pt = base + w*4+sub covers
        // [base, base+32) exactly once
        if (pt >= end || l >= CH / 4) continue;

        float4 s = g_sorted[pt];
        int idx = __float_as_int(s.w);

        float px = (s.x / 1.5f + 1.0f) * 63.5f;
        float py = (s.y / 1.5f + 1.0f) * 63.5f;
        float pz = (s.z / 1.5f + 1.0f) * 63.5f;
        float flx = floorf(px), fly = floorf(py), flz = floorf(pz);
        float fx = px - flx, fy = py - fly, fz = pz - flz;
        int x0 = min(max((int)flx, 0), 126);
        int y0 = min(max((int)fly, 0), 126);
        int z0 = min(max((int)flz, 0), 126);

        float wx1 = fx, wx0 = 1.f - fx;
        float wy1 = fy, wy0 = 1.f - fy;
        float wz1 = fz, wz0 = 1.f - fz;
        float w00 = wz0 * wy0, w01 = wz0 * wy1, w10 = wz1 * wy0, w11 = wz1 * wy1;

        const float4* base = (const float4*)vol +
                             (((size_t)z0 * 128 + y0) * 128 + x0) * (CP / 4) + l;
        const size_t DX = CP / 4;
        const size_t DY = (size_t)128 * (CP / 4);
        const size_t DZ = (size_t)128 * 128 * (CP / 4);

        float4 v000 = base[0];
        float4 v001 = base[DX];
        float4 v010 = base[DY];
        float4 v011 = base[DY + DX];
        float4 v100 = base[DZ];
        float4 v101 = base[DZ + DX];
        float4 v110 = base[DZ + DY];
        float4 v111 = base[DZ + DY + DX];

        float4 r;
        r.x = w00 * (wx0 * v000.x + wx1 * v001.x) + w01 * (wx0 * v010.x + wx1 * v011.x) +
              w10 * (wx0 * v100.x + wx1 * v101.x) + w11 * (wx0 * v110.x + wx1 * v111.x);
        r.y = w00 * (wx0 * v000.y + wx1 * v001.y) + w01 * (wx0 * v010.y + wx1 * v011.y) +
              w10 * (wx0 * v100.y + wx1 * v101.y) + w11 * (wx0 * v110.y + wx1 * v111.y);
        r.z = w00 * (wx0 * v000.z + wx1 * v001.z) + w01 * (wx0 * v010.z + wx1 * v011.z) +
              w10 * (wx0 * v100.z + wx1 * v101.z) + w11 * (wx0 * v110.z + wx1 * v111.z);
        r.w = w00 * (wx0 * v000.w + wx1 * v001.w) + w01 * (wx0 * v010.w + wx1 * v011.w) +
              w10 * (wx0 * v100.w + wx1 * v101.w) + w11 * (wx0 * v110.w + wx1 * v111.w);

        __stcs((float4*)(out + (size_t)idx * CH) + l, r);
    }
}

extern "C" void kernel_launch(void* const* d_in, const int* in_sizes, int n_in,
                              void* d_out, int out_size) {
    const float* approx = (const float*)d_in[0];   // (28,16,16,16)
    const float* det0   = (const float*)d_in[1];   // (7,28,16,16,16)
    const float* det1   = (const float*)d_in[2];   // (7,28,32,32,32)
    const float* det2   = (const float*)d_in[3];   // (7,28,64,64,64)
    const float* xyz    = (const float*)d_in[4];   // (N,3)
    int N = in_sizes[4] / 3;

    float *vol1, *vol2, *volF;
    cudaGetSymbolAddress((void**)&vol1, g_vol1);
    cudaGetSymbolAddress((void**)&vol2, g_vol2);
    cudaGetSymbolAddress((void**)&volF, g_volF);

    // 3D-tile sort chain
    zero_hist_kernel<<<1, 1024>>>();
    hist_kernel<<<448, 256>>>(xyz, N);
    scan_kernel<<<1, 1024>>>();
    scatter_kernel<<<(N + SCHUNK - 1) / SCHUNK, 256>>>(xyz, N);

    {   // level 0: 16 -> 32
        int n = CH * 16 * 16 * 16;
        idwt_small<16><<<(n + 255) / 256, 256>>>(approx, det0, vol1);
    }
    {   // level 1: 32 -> 64
        int n = CH * 32 * 32 * 32;
        idwt_small<32><<<(n + 255) / 256, 256>>>(vol1, det1, vol2);
    }
    // level 2: 64 -> 128, fused transpose to padded fp32 (z,y,x,32), z desc
    idwt_final<<<64 * 64 * 8, 256>>>(vol2, det2, volF);

    // trilinear gather: one block per 3D tile (L1-resident footprint)
    query_kernel<<<NBIN, 256>>>(volF, (float*)d_out);
}